// round 16
// baseline (speedup 1.0000x reference)
#include <cuda_runtime.h>
#include <cuda_fp16.h>
#include <cstdint>

typedef unsigned long long u64;

#define BATCH     8192
#define IN_DIM    784
#define INP       800            // padded IN_DIM (multiple of 32)
#define HID       128
#define CLASS_NUM 10
#define TREES     16
#define INTERNAL  255
#define TOTAL     511
#define DEPTH     9

// ---------------- static scratch (no allocations) ---------------------------
__device__ float          g_feats[BATCH * HID];
__device__ unsigned short g_fH[BATCH * HID];        // feats fp16 (tree A operand)
__device__ unsigned short g_nwH[TREES * 256 * HID]; // nodeW fp16
__device__ unsigned short g_xH[BATCH * INP];        // X fp16
__device__ unsigned short g_w1H[HID * INP];         // W1^T fp16

// ---------------- helpers ----------------------------------------------------
__device__ __forceinline__ float sigmoidf_(float x) { return 1.f / (1.f + __expf(-x)); }

__device__ __forceinline__ unsigned short f16b(float x) {
    return __half_as_ushort(__float2half_rn(x));
}

__device__ __forceinline__ uint32_t smem_u32(const void* p) {
    uint32_t a;
    asm("{ .reg .u64 t; cvta.to.shared.u64 t, %1; cvt.u32.u64 %0, t; }" : "=r"(a) : "l"(p));
    return a;
}
__device__ __forceinline__ void cp16(uint32_t dst, const void* src) {
    asm volatile("cp.async.cg.shared.global [%0], [%1], 16;" :: "r"(dst), "l"(src));
}
__device__ __forceinline__ void cp_commit() {
    asm volatile("cp.async.commit_group;" ::: "memory");
}
__device__ __forceinline__ void cp_wait0() {
    asm volatile("cp.async.wait_group 0;" ::: "memory");
}
__device__ __forceinline__ void stcs2(float* p, float2 v) {
    asm volatile("st.global.cs.v2.f32 [%0], {%1, %2};" :: "l"(p), "f"(v.x), "f"(v.y)
                 : "memory");
}

// ldmatrix x4: four 8x8 b16 matrices
__device__ __forceinline__ void ldsm4(uint32_t& r0, uint32_t& r1, uint32_t& r2,
                                      uint32_t& r3, uint32_t addr) {
    asm volatile("ldmatrix.sync.aligned.m8n8.x4.shared.b16 {%0,%1,%2,%3}, [%4];"
                 : "=r"(r0), "=r"(r1), "=r"(r2), "=r"(r3) : "r"(addr));
}

// warp-level fp16 MMA: D[16x8] += A[16x16] * B[16x8]  (fp32 accum)
__device__ __forceinline__ void mma16816h(float* c, uint32_t a0, uint32_t a1,
                                          uint32_t a2, uint32_t a3,
                                          uint32_t b0, uint32_t b1) {
    asm volatile(
        "mma.sync.aligned.m16n8k16.row.col.f32.f16.f16.f32 "
        "{%0,%1,%2,%3}, {%4,%5,%6,%7}, {%8,%9}, {%0,%1,%2,%3};"
        : "+f"(c[0]), "+f"(c[1]), "+f"(c[2]), "+f"(c[3])
        : "r"(a0), "r"(a1), "r"(a2), "r"(a3), "r"(b0), "r"(b1));
}

// ---------------------------------------------------------------------------
// conversion kernels
// ---------------------------------------------------------------------------
__global__ __launch_bounds__(256) void conv_nodeW_kernel(const float* __restrict__ nodeW) {
    int idx  = blockIdx.x * 256 + threadIdx.x;
    int k    = idx & 127;
    int node = (idx >> 7) & 255;
    int t    = idx >> 15;
    float w  = (node < INTERNAL) ? nodeW[((size_t)t * INTERNAL + node) * HID + k] : 0.f;
    g_nwH[idx] = f16b(w);
}

__global__ __launch_bounds__(256) void conv_X_kernel(const float* __restrict__ X) {
    int gid = blockIdx.x * 256 + threadIdx.x;               // 0 .. BATCH*200-1
    int row = gid / 200;
    int k4  = (gid - row * 200) * 4;
    if (row >= BATCH) return;
    float v[4];
    if (k4 + 4 <= IN_DIM) {
        float4 x = *(const float4*)&X[(size_t)row * IN_DIM + k4];
        v[0] = x.x; v[1] = x.y; v[2] = x.z; v[3] = x.w;
    } else {
#pragma unroll
        for (int j = 0; j < 4; j++)
            v[j] = (k4 + j < IN_DIM) ? X[(size_t)row * IN_DIM + k4 + j] : 0.f;
    }
    uint2 hv;
    hv.x = (uint32_t)f16b(v[0]) | ((uint32_t)f16b(v[1]) << 16);
    hv.y = (uint32_t)f16b(v[2]) | ((uint32_t)f16b(v[3]) << 16);
    *(uint2*)&g_xH[(size_t)row * INP + k4] = hv;
}

__global__ __launch_bounds__(256) void conv_W1_kernel(const float* __restrict__ W1) {
    int n = blockIdx.x;
    for (int k4 = threadIdx.x * 4; k4 < INP; k4 += 256 * 4) {
        float v[4];
#pragma unroll
        for (int j = 0; j < 4; j++)
            v[j] = (k4 + j < IN_DIM) ? W1[(size_t)(k4 + j) * HID + n] : 0.f;
        uint2 hv;
        hv.x = (uint32_t)f16b(v[0]) | ((uint32_t)f16b(v[1]) << 16);
        hv.y = (uint32_t)f16b(v[2]) | ((uint32_t)f16b(v[3]) << 16);
        *(uint2*)&g_w1H[(size_t)n * INP + k4] = hv;
    }
}

// ---------------------------------------------------------------------------
// GEMM1 (tensor core, single-term fp16): feats = relu(X @ W1 + b1)
// CTA: 64 batch x 128 hid, 512 threads (16 warps = 4 wm x 4 wn, 16b x 32n)
// ---------------------------------------------------------------------------
#define KSTR  20                 // u32 per k-row: conflict-free, 16B aligned
#define G_NC  (INP / 32)         // 25
#define G_MB  64

#define G_OFF_BIAS 0
#define G_OFF_T    512
#define G_XSZ      (G_MB * KSTR * 4)    // 5120
#define G_WSZ      (128 * KSTR * 4)     // 10240
#define G_BUF      (G_XSZ + G_WSZ)           // 15360
#define G_SMEM     (G_OFF_T + 2 * G_BUF)     // 31232

__global__ __launch_bounds__(512) void gemm1_mma_kernel(const float* __restrict__ b1) {
    extern __shared__ char smem[];
    float* sBias = (float*)(smem + G_OFF_BIAS);
    const uint32_t sb = smem_u32(smem);

    const int tid  = threadIdx.x;
    const int wid  = tid >> 5;
    const int lane = tid & 31;
    const int m0   = blockIdx.x * G_MB;

    if (tid < HID) sBias[tid] = b1[tid];

    const int wm  = wid >> 2;        // 0..3 : 16-batch tile
    const int wn  = wid & 3;         // 0..3 : 32-hid tile
    const int grp = lane >> 2;       // 0..7
    const int kp  = lane & 3;        // 0..3

    const int lrow = lane & 15;
    const int lcol = (lane >> 4) * 4;
    const uint32_t aOff = (uint32_t)(((wm * 16 + lrow) * KSTR + lcol) * 4);
    uint32_t bOff[2];
#pragma unroll
    for (int pi = 0; pi < 2; pi++)
        bOff[pi] = (uint32_t)(((wn * 32 + pi * 16 + lrow) * KSTR + lcol) * 4);

    auto issue = [&](int c, int buf) {
        uint32_t base = sb + G_OFF_T + buf * G_BUF;
        if (tid < 256) {                            // X: 64 x 4 = 256 slots
            int b = tid >> 2, q = tid & 3;
            size_t go = (size_t)(m0 + b) * INP + c * 32 + q * 8;
            uint32_t so = (uint32_t)((b * KSTR + q * 4) * 4);
            cp16(base + so, g_xH + go);
        }
        {
            int n = tid >> 2, q = tid & 3;          // W1: 128 x 4 = 512 slots
            size_t go = (size_t)n * INP + c * 32 + q * 8;
            uint32_t so = (uint32_t)((n * KSTR + q * 4) * 4);
            cp16(base + G_XSZ + so, g_w1H + go);
        }
    };

    float acc[4][4];
#pragma unroll
    for (int ni = 0; ni < 4; ni++)
#pragma unroll
        for (int r = 0; r < 4; r++) acc[ni][r] = 0.f;

    issue(0, 0);
    cp_commit();

    for (int c = 0; c < G_NC; c++) {
        cp_wait0();
        __syncthreads();
        if (c + 1 < G_NC) { issue(c + 1, (c + 1) & 1); cp_commit(); }

        uint32_t xhB = sb + G_OFF_T + (c & 1) * G_BUF;
        uint32_t whB = xhB + G_XSZ;

#pragma unroll
        for (int s = 0; s < 2; s++) {
            uint32_t sB = s * 32;
            uint32_t ah0, ah1, ah2, ah3;
            ldsm4(ah0, ah1, ah2, ah3, xhB + aOff + sB);
#pragma unroll
            for (int pi = 0; pi < 2; pi++) {
                uint32_t h0, h1, h2, h3;
                ldsm4(h0, h1, h2, h3, whB + bOff[pi] + sB);
                mma16816h(acc[2 * pi],     ah0, ah1, ah2, ah3, h0, h2);
                mma16816h(acc[2 * pi + 1], ah0, ah1, ah2, ah3, h1, h3);
            }
        }
    }

    // epilogue: bias + relu -> feats fp32 + fp16
    const int rowA = m0 + wm * 16 + grp;
#pragma unroll
    for (int ni = 0; ni < 4; ni++) {
        int col = wn * 32 + ni * 8 + kp * 2;
        float c0 = sBias[col], c1 = sBias[col + 1];
#pragma unroll
        for (int half = 0; half < 2; half++) {
            int row = rowA + half * 8;
            float v0 = acc[ni][2 * half]     + c0;
            float v1 = acc[ni][2 * half + 1] + c1;
            v0 = v0 > 0.f ? v0 : 0.f;
            v1 = v1 > 0.f ? v1 : 0.f;
            *(float2*)&g_feats[(size_t)row * HID + col] = make_float2(v0, v1);
            uint32_t hw = (uint32_t)f16b(v0) | ((uint32_t)f16b(v1) << 16);
            *(uint32_t*)&g_fH[(size_t)row * HID + col] = hw;
        }
    }
}

// ---------------------------------------------------------------------------
// Prediction: pred = feats @ W2 + b2   (32 rows/block, grid 256)
// W2 staged TRANSPOSED [c][d]; float4 inner loop (32 steps).
// ---------------------------------------------------------------------------
#define P_FS 136   // sF row stride (floats): multiple of 4 -> aligned float4
__global__ __launch_bounds__(256) void pred_kernel(const float* __restrict__ W2,
                                                   const float* __restrict__ b2,
                                                   float* __restrict__ pred) {
    __shared__ float sF[32 * P_FS];
    __shared__ float sW2T[CLASS_NUM * HID];    // [c][d]
    const int tid = threadIdx.x;
    const int b0  = blockIdx.x * 32;
#pragma unroll
    for (int it = 0; it < 16; it++) {
        int e = it * 256 + tid;
        int r = e >> 7, d = e & 127;
        sF[r * P_FS + d] = g_feats[(size_t)(b0 + r) * HID + d];
    }
    for (int e = tid; e < HID * CLASS_NUM; e += 256) {
        int d = e / CLASS_NUM, c = e % CLASS_NUM;
        sW2T[c * HID + d] = W2[e];
    }
    __syncthreads();
    for (int o = tid; o < 32 * CLASS_NUM; o += 256) {
        int r = o / CLASS_NUM, c = o % CLASS_NUM;
        float s = b2[c];
        const float4* f4 = (const float4*)&sF[r * P_FS];
        const float4* w4 = (const float4*)&sW2T[c * HID];
#pragma unroll
        for (int d = 0; d < HID / 4; d++) {
            float4 a = f4[d], b = w4[d];
            s += a.x * b.x + a.y * b.y + a.z * b.z + a.w * b.w;
        }
        pred[(size_t)(b0 + r) * CLASS_NUM + c] = s;
    }
}

// ---------------------------------------------------------------------------
// Tree kernel (fp16 single-term: fh·nh, ldmatrix, cp.async dbuf):
//   per (tree, 64-batch tile): D[64b x 256n] -> sigmoid -> dec tile -> DFS
//   dec tile ALIASES the MMA tile buffers -> 2 CTAs/SM
// ---------------------------------------------------------------------------
#define MB    64
#define DSTR  68
#define T_NC  (HID / 32)               // 4

#define T_OFF_NB  0
#define T_OFF_T   1024
#define T_FSZ     (64 * KSTR * 4)            // 5120
#define T_WSZ     (256 * KSTR * 4)           // 20480
#define T_BUF     (T_FSZ + T_WSZ)            // 25600
#define T_DECSZ   (256 * DSTR * 4)           // 69632
#define TREE_SMEM (T_OFF_T + T_DECSZ)        // 70656

template <int LVL>
__device__ __forceinline__ void emit2(float* __restrict__ outCol,
                                      const float* __restrict__ decCol,
                                      int node, float2 v) {
    stcs2(&outCol[(size_t)node * BATCH], v);
    if constexpr (LVL < DEPTH - 1) {
        float2 d = *(const float2*)&decCol[node * DSTR];
        emit2<LVL + 1>(outCol, decCol, 2 * node + 1,
                       make_float2(v.x * d.x, v.y * d.y));
        emit2<LVL + 1>(outCol, decCol, 2 * node + 2,
                       make_float2(v.x * (1.f - d.x), v.y * (1.f - d.y)));
    }
}

__global__ __launch_bounds__(512, 2) void tree_mma_kernel(const float* __restrict__ nodeb,
                                                          float* __restrict__ outAll) {
    extern __shared__ char smem[];
    float* sNB  = (float*)(smem + T_OFF_NB);
    float* decS = (float*)(smem + T_OFF_T);   // aliases tile buffers (post-MMA)
    const uint32_t sb = smem_u32(smem);

    const int tid  = threadIdx.x;
    const int wid  = tid >> 5;
    const int lane = tid & 31;
    const int t    = blockIdx.y;
    const int b0   = blockIdx.x * MB;
    const size_t wbase = (size_t)t * 256 * HID;

    if (tid < 256)
        sNB[tid] = (tid < INTERNAL) ? nodeb[t * INTERNAL + tid] : 0.f;

    const int wb  = wid >> 2;      // 0..3: 16-batch tile
    const int wn  = wid & 3;       // 0..3: 64-node tile
    const int grp = lane >> 2;
    const int kp  = lane & 3;

    const int lrow = lane & 15;
    const int lcol = (lane >> 4) * 4;
    const uint32_t aOff = (uint32_t)(((wb * 16 + lrow) * KSTR + lcol) * 4);
    uint32_t bOff[4];
#pragma unroll
    for (int pi = 0; pi < 4; pi++)
        bOff[pi] = (uint32_t)(((wn * 64 + pi * 16 + lrow) * KSTR + lcol) * 4);

    auto issue = [&](int c, int buf) {
        uint32_t base = sb + T_OFF_T + buf * T_BUF;
        if (tid < 256) {               // feats fp16: 64 x 4 = 256 slots
            int b = tid >> 2, q = tid & 3;
            size_t go = (size_t)(b0 + b) * HID + c * 32 + q * 8;
            uint32_t so = (uint32_t)((b * KSTR + q * 4) * 4);
            cp16(base + so, g_fH + go);
        }
#pragma unroll
        for (int rep = 0; rep < 2; rep++) {   // nodeW fp16: 256 x 4 = 1024 slots
            int i = tid + rep * 512;
            int n = i >> 2, q = i & 3;
            size_t go = wbase + (size_t)n * HID + c * 32 + q * 8;
            uint32_t so = (uint32_t)((n * KSTR + q * 4) * 4);
            cp16(base + T_FSZ + so, g_nwH + go);
        }
    };

    float acc[8][4];
#pragma unroll
    for (int ni = 0; ni < 8; ni++)
#pragma unroll
        for (int r = 0; r < 4; r++) acc[ni][r] = 0.f;

    issue(0, 0);
    cp_commit();

#pragma unroll
    for (int c = 0; c < T_NC; c++) {
        cp_wait0();
        __syncthreads();
        if (c + 1 < T_NC) { issue(c + 1, (c + 1) & 1); cp_commit(); }

        uint32_t fhB = sb + T_OFF_T + (c & 1) * T_BUF;
        uint32_t whB = fhB + T_FSZ;

#pragma unroll
        for (int s = 0; s < 2; s++) {
            uint32_t sB = s * 32;
            uint32_t ah0, ah1, ah2, ah3;
            ldsm4(ah0, ah1, ah2, ah3, fhB + aOff + sB);
#pragma unroll
            for (int pi = 0; pi < 4; pi++) {
                uint32_t h0, h1, h2, h3;
                ldsm4(h0, h1, h2, h3, whB + bOff[pi] + sB);
                mma16816h(acc[2 * pi],     ah0, ah1, ah2, ah3, h0, h2);
                mma16816h(acc[2 * pi + 1], ah0, ah1, ah2, ah3, h1, h3);
            }
        }
    }

    // dec tile aliases the MMA buffers: all compute must be done first
    __syncthreads();

    // ---- epilogue: + bias, sigmoid -> dec tile ----
#pragma unroll
    for (int ni = 0; ni < 8; ni++) {
        int nbase = wn * 64 + ni * 8 + kp * 2;
        int bb    = wb * 16 + grp;
#pragma unroll
        for (int r = 0; r < 4; r++) {
            int node = nbase + (r & 1);
            int b    = bb + (r >> 1) * 8;
            decS[node * DSTR + b] = sigmoidf_(acc[ni][r] + sNB[node]);
        }
    }
    __syncthreads();

    // ---- tree path products: 32 col-pairs x 16 groups, float2 ----
    {
        const int colp = (tid & 31) * 2;       // 0,2,..,62
        const int q    = tid >> 5;             // 0..15
        float* outCol = outAll + (size_t)t * TOTAL * BATCH + (b0 + colp);
        const float* decCol = decS + colp;

        if (q < 8) {
            // subtree rooted at level-3 node 7+q: 63 nodes
            const int rN = 7 + q;
            float2 v = make_float2(1.f, 1.f);
            int x = rN;
            while (x) {
                int p = (x - 1) >> 1;
                float2 d = *(const float2*)&decCol[p * DSTR];
                if (x == 2 * p + 1) { v.x *= d.x;        v.y *= d.y; }
                else                { v.x *= 1.f - d.x;  v.y *= 1.f - d.y; }
                x = p;
            }
            emit2<3>(outCol, decCol, rN, v);
        } else {
            // top 7 nodes (levels 0..2): group q-8 handles node q-8
            const int n = q - 8;
            if (n < 7) {
                float2 v = make_float2(1.f, 1.f);
                int x = n;
                while (x) {
                    int p = (x - 1) >> 1;
                    float2 d = *(const float2*)&decCol[p * DSTR];
                    if (x == 2 * p + 1) { v.x *= d.x;        v.y *= d.y; }
                    else                { v.x *= 1.f - d.x;  v.y *= 1.f - d.y; }
                    x = p;
                }
                stcs2(&outCol[(size_t)n * BATCH], v);
            }
        }
    }
}

// ---------------------------------------------------------------------------
extern "C" void kernel_launch(void* const* d_in, const int* in_sizes, int n_in,
                              void* d_out, int out_size) {
    const float* X     = (const float*)d_in[0];
    const float* W1    = (const float*)d_in[1];
    const float* b1    = (const float*)d_in[2];
    const float* W2    = (const float*)d_in[3];
    const float* b2    = (const float*)d_in[4];
    const float* nodeW = (const float*)d_in[5];
    const float* nodeb = (const float*)d_in[6];

    float* pred   = (float*)d_out;                               // [8192, 10]
    float* outAll = (float*)d_out + (size_t)BATCH * CLASS_NUM;   // [16, 511, 8192]

    cudaFuncSetAttribute(tree_mma_kernel, cudaFuncAttributeMaxDynamicSharedMemorySize,
                         TREE_SMEM);
    cudaFuncSetAttribute(gemm1_mma_kernel, cudaFuncAttributeMaxDynamicSharedMemorySize,
                         G_SMEM);

    conv_X_kernel<<<(BATCH * 200 + 255) / 256, 256>>>(X);
    conv_W1_kernel<<<HID, 256>>>(W1);
    conv_nodeW_kernel<<<TREES * 256 * HID / 256, 256>>>(nodeW);
    gemm1_mma_kernel<<<BATCH / G_MB, 512, G_SMEM>>>(b1);
    tree_mma_kernel<<<dim3(BATCH / MB, TREES), 512, TREE_SMEM>>>(nodeb, outAll);
    pred_kernel<<<BATCH / 32, 256>>>(W2, b2, pred);
}

// round 17
// speedup vs baseline: 1.0689x; 1.0689x over previous
#include <cuda_runtime.h>
#include <cuda_fp16.h>
#include <cstdint>

typedef unsigned long long u64;

#define BATCH     8192
#define IN_DIM    784
#define INP       800            // padded IN_DIM (multiple of 32)
#define HID       128
#define CLASS_NUM 10
#define TREES     16
#define INTERNAL  255
#define TOTAL     511
#define DEPTH     9

// ---------------- static scratch (no allocations) ---------------------------
__device__ float          g_feats[BATCH * HID];
__device__ unsigned short g_fH[BATCH * HID];        // feats fp16 (tree A operand)
__device__ unsigned short g_nwH[TREES * 256 * HID]; // nodeW fp16
__device__ unsigned short g_xH[BATCH * INP];        // X fp16
__device__ unsigned short g_w1H[HID * INP];         // W1^T fp16

// ---------------- helpers ----------------------------------------------------
__device__ __forceinline__ float sigmoidf_(float x) { return 1.f / (1.f + __expf(-x)); }

__device__ __forceinline__ unsigned short f16b(float x) {
    return __half_as_ushort(__float2half_rn(x));
}

__device__ __forceinline__ uint32_t smem_u32(const void* p) {
    uint32_t a;
    asm("{ .reg .u64 t; cvta.to.shared.u64 t, %1; cvt.u32.u64 %0, t; }" : "=r"(a) : "l"(p));
    return a;
}
__device__ __forceinline__ void cp16(uint32_t dst, const void* src) {
    asm volatile("cp.async.cg.shared.global [%0], [%1], 16;" :: "r"(dst), "l"(src));
}
__device__ __forceinline__ void cp_commit() {
    asm volatile("cp.async.commit_group;" ::: "memory");
}
__device__ __forceinline__ void cp_wait0() {
    asm volatile("cp.async.wait_group 0;" ::: "memory");
}
__device__ __forceinline__ void stcs2(float* p, float2 v) {
    asm volatile("st.global.cs.v2.f32 [%0], {%1, %2};" :: "l"(p), "f"(v.x), "f"(v.y)
                 : "memory");
}

// ldmatrix x4: four 8x8 b16 matrices
__device__ __forceinline__ void ldsm4(uint32_t& r0, uint32_t& r1, uint32_t& r2,
                                      uint32_t& r3, uint32_t addr) {
    asm volatile("ldmatrix.sync.aligned.m8n8.x4.shared.b16 {%0,%1,%2,%3}, [%4];"
                 : "=r"(r0), "=r"(r1), "=r"(r2), "=r"(r3) : "r"(addr));
}

// warp-level fp16 MMA: D[16x8] += A[16x16] * B[16x8]  (fp32 accum)
__device__ __forceinline__ void mma16816h(float* c, uint32_t a0, uint32_t a1,
                                          uint32_t a2, uint32_t a3,
                                          uint32_t b0, uint32_t b1) {
    asm volatile(
        "mma.sync.aligned.m16n8k16.row.col.f32.f16.f16.f32 "
        "{%0,%1,%2,%3}, {%4,%5,%6,%7}, {%8,%9}, {%0,%1,%2,%3};"
        : "+f"(c[0]), "+f"(c[1]), "+f"(c[2]), "+f"(c[3])
        : "r"(a0), "r"(a1), "r"(a2), "r"(a3), "r"(b0), "r"(b1));
}

// ---------------------------------------------------------------------------
// conversion kernels
// ---------------------------------------------------------------------------
__global__ __launch_bounds__(256) void conv_nodeW_kernel(const float* __restrict__ nodeW) {
    int idx  = blockIdx.x * 256 + threadIdx.x;
    int k    = idx & 127;
    int node = (idx >> 7) & 255;
    int t    = idx >> 15;
    float w  = (node < INTERNAL) ? nodeW[((size_t)t * INTERNAL + node) * HID + k] : 0.f;
    g_nwH[idx] = f16b(w);
}

__global__ __launch_bounds__(256) void conv_X_kernel(const float* __restrict__ X) {
    int gid = blockIdx.x * 256 + threadIdx.x;               // 0 .. BATCH*200-1
    int row = gid / 200;
    int k4  = (gid - row * 200) * 4;
    if (row >= BATCH) return;
    float v[4];
    if (k4 + 4 <= IN_DIM) {
        float4 x = *(const float4*)&X[(size_t)row * IN_DIM + k4];
        v[0] = x.x; v[1] = x.y; v[2] = x.z; v[3] = x.w;
    } else {
#pragma unroll
        for (int j = 0; j < 4; j++)
            v[j] = (k4 + j < IN_DIM) ? X[(size_t)row * IN_DIM + k4 + j] : 0.f;
    }
    uint2 hv;
    hv.x = (uint32_t)f16b(v[0]) | ((uint32_t)f16b(v[1]) << 16);
    hv.y = (uint32_t)f16b(v[2]) | ((uint32_t)f16b(v[3]) << 16);
    *(uint2*)&g_xH[(size_t)row * INP + k4] = hv;
}

__global__ __launch_bounds__(256) void conv_W1_kernel(const float* __restrict__ W1) {
    int n = blockIdx.x;
    for (int k4 = threadIdx.x * 4; k4 < INP; k4 += 256 * 4) {
        float v[4];
#pragma unroll
        for (int j = 0; j < 4; j++)
            v[j] = (k4 + j < IN_DIM) ? W1[(size_t)(k4 + j) * HID + n] : 0.f;
        uint2 hv;
        hv.x = (uint32_t)f16b(v[0]) | ((uint32_t)f16b(v[1]) << 16);
        hv.y = (uint32_t)f16b(v[2]) | ((uint32_t)f16b(v[3]) << 16);
        *(uint2*)&g_w1H[(size_t)n * INP + k4] = hv;
    }
}

// ---------------------------------------------------------------------------
// GEMM1 (tensor core, single-term fp16): feats = relu(X @ W1 + b1)
// CTA: 64 batch x 128 hid, 512 threads (16 warps = 4 wm x 4 wn, 16b x 32n)
// ---------------------------------------------------------------------------
#define KSTR  20                 // u32 per k-row: conflict-free, 16B aligned
#define G_NC  (INP / 32)         // 25
#define G_MB  64

#define G_OFF_BIAS 0
#define G_OFF_T    512
#define G_XSZ      (G_MB * KSTR * 4)    // 5120
#define G_WSZ      (128 * KSTR * 4)     // 10240
#define G_BUF      (G_XSZ + G_WSZ)           // 15360
#define G_SMEM     (G_OFF_T + 2 * G_BUF)     // 31232

__global__ __launch_bounds__(512) void gemm1_mma_kernel(const float* __restrict__ b1) {
    extern __shared__ char smem[];
    float* sBias = (float*)(smem + G_OFF_BIAS);
    const uint32_t sb = smem_u32(smem);

    const int tid  = threadIdx.x;
    const int wid  = tid >> 5;
    const int lane = tid & 31;
    const int m0   = blockIdx.x * G_MB;

    if (tid < HID) sBias[tid] = b1[tid];

    const int wm  = wid >> 2;        // 0..3 : 16-batch tile
    const int wn  = wid & 3;         // 0..3 : 32-hid tile
    const int grp = lane >> 2;       // 0..7
    const int kp  = lane & 3;        // 0..3

    const int lrow = lane & 15;
    const int lcol = (lane >> 4) * 4;
    const uint32_t aOff = (uint32_t)(((wm * 16 + lrow) * KSTR + lcol) * 4);
    uint32_t bOff[2];
#pragma unroll
    for (int pi = 0; pi < 2; pi++)
        bOff[pi] = (uint32_t)(((wn * 32 + pi * 16 + lrow) * KSTR + lcol) * 4);

    auto issue = [&](int c, int buf) {
        uint32_t base = sb + G_OFF_T + buf * G_BUF;
        if (tid < 256) {                            // X: 64 x 4 = 256 slots
            int b = tid >> 2, q = tid & 3;
            size_t go = (size_t)(m0 + b) * INP + c * 32 + q * 8;
            uint32_t so = (uint32_t)((b * KSTR + q * 4) * 4);
            cp16(base + so, g_xH + go);
        }
        {
            int n = tid >> 2, q = tid & 3;          // W1: 128 x 4 = 512 slots
            size_t go = (size_t)n * INP + c * 32 + q * 8;
            uint32_t so = (uint32_t)((n * KSTR + q * 4) * 4);
            cp16(base + G_XSZ + so, g_w1H + go);
        }
    };

    float acc[4][4];
#pragma unroll
    for (int ni = 0; ni < 4; ni++)
#pragma unroll
        for (int r = 0; r < 4; r++) acc[ni][r] = 0.f;

    issue(0, 0);
    cp_commit();

    for (int c = 0; c < G_NC; c++) {
        cp_wait0();
        __syncthreads();
        if (c + 1 < G_NC) { issue(c + 1, (c + 1) & 1); cp_commit(); }

        uint32_t xhB = sb + G_OFF_T + (c & 1) * G_BUF;
        uint32_t whB = xhB + G_XSZ;

#pragma unroll
        for (int s = 0; s < 2; s++) {
            uint32_t sB = s * 32;
            uint32_t ah0, ah1, ah2, ah3;
            ldsm4(ah0, ah1, ah2, ah3, xhB + aOff + sB);
#pragma unroll
            for (int pi = 0; pi < 2; pi++) {
                uint32_t h0, h1, h2, h3;
                ldsm4(h0, h1, h2, h3, whB + bOff[pi] + sB);
                mma16816h(acc[2 * pi],     ah0, ah1, ah2, ah3, h0, h2);
                mma16816h(acc[2 * pi + 1], ah0, ah1, ah2, ah3, h1, h3);
            }
        }
    }

    // epilogue: bias + relu -> feats fp32 + fp16
    const int rowA = m0 + wm * 16 + grp;
#pragma unroll
    for (int ni = 0; ni < 4; ni++) {
        int col = wn * 32 + ni * 8 + kp * 2;
        float c0 = sBias[col], c1 = sBias[col + 1];
#pragma unroll
        for (int half = 0; half < 2; half++) {
            int row = rowA + half * 8;
            float v0 = acc[ni][2 * half]     + c0;
            float v1 = acc[ni][2 * half + 1] + c1;
            v0 = v0 > 0.f ? v0 : 0.f;
            v1 = v1 > 0.f ? v1 : 0.f;
            *(float2*)&g_feats[(size_t)row * HID + col] = make_float2(v0, v1);
            uint32_t hw = (uint32_t)f16b(v0) | ((uint32_t)f16b(v1) << 16);
            *(uint32_t*)&g_fH[(size_t)row * HID + col] = hw;
        }
    }
}

// ---------------------------------------------------------------------------
// Prediction: pred = feats @ W2 + b2   (32 rows/block, grid 256)
// W2 staged TRANSPOSED [c][d] with PADDED stride (conflict-free float4).
// ---------------------------------------------------------------------------
#define P_FS 136   // sF row stride (floats)
#define P_WS 132   // sW2T row stride (floats): 528B = 33 x 16B, rotates banks
__global__ __launch_bounds__(256) void pred_kernel(const float* __restrict__ W2,
                                                   const float* __restrict__ b2,
                                                   float* __restrict__ pred) {
    __shared__ float sF[32 * P_FS];
    __shared__ float sW2T[CLASS_NUM * P_WS];   // [c][d], padded
    const int tid = threadIdx.x;
    const int b0  = blockIdx.x * 32;
#pragma unroll
    for (int it = 0; it < 16; it++) {
        int e = it * 256 + tid;
        int r = e >> 7, d = e & 127;
        sF[r * P_FS + d] = g_feats[(size_t)(b0 + r) * HID + d];
    }
    for (int e = tid; e < HID * CLASS_NUM; e += 256) {
        int d = e / CLASS_NUM, c = e % CLASS_NUM;
        sW2T[c * P_WS + d] = W2[e];
    }
    __syncthreads();
    for (int o = tid; o < 32 * CLASS_NUM; o += 256) {
        int r = o / CLASS_NUM, c = o % CLASS_NUM;
        float s = b2[c];
        const float4* f4 = (const float4*)&sF[r * P_FS];
        const float4* w4 = (const float4*)&sW2T[c * P_WS];
#pragma unroll
        for (int d = 0; d < HID / 4; d++) {
            float4 a = f4[d], b = w4[d];
            s += a.x * b.x + a.y * b.y + a.z * b.z + a.w * b.w;
        }
        pred[(size_t)(b0 + r) * CLASS_NUM + c] = s;
    }
}

// ---------------------------------------------------------------------------
// Tree kernel (fp16 single-term: fh·nh, ldmatrix, cp.async dbuf):
//   per (tree, 64-batch tile): D[64b x 256n] -> sigmoid -> dec tile -> DFS
//   dec tile ALIASES the MMA tile buffers -> 2 CTAs/SM
// ---------------------------------------------------------------------------
#define MB    64
#define DSTR  68
#define T_NC  (HID / 32)               // 4

#define T_OFF_NB  0
#define T_OFF_T   1024
#define T_FSZ     (64 * KSTR * 4)            // 5120
#define T_WSZ     (256 * KSTR * 4)           // 20480
#define T_BUF     (T_FSZ + T_WSZ)            // 25600
#define T_DECSZ   (256 * DSTR * 4)           // 69632
#define TREE_SMEM (T_OFF_T + T_DECSZ)        // 70656

template <int LVL>
__device__ __forceinline__ void emit2(float* __restrict__ outCol,
                                      const float* __restrict__ decCol,
                                      int node, float2 v) {
    stcs2(&outCol[(size_t)node * BATCH], v);
    if constexpr (LVL < DEPTH - 1) {
        float2 d = *(const float2*)&decCol[node * DSTR];
        emit2<LVL + 1>(outCol, decCol, 2 * node + 1,
                       make_float2(v.x * d.x, v.y * d.y));
        emit2<LVL + 1>(outCol, decCol, 2 * node + 2,
                       make_float2(v.x * (1.f - d.x), v.y * (1.f - d.y)));
    }
}

__global__ __launch_bounds__(512, 2) void tree_mma_kernel(const float* __restrict__ nodeb,
                                                          float* __restrict__ outAll) {
    extern __shared__ char smem[];
    float* sNB  = (float*)(smem + T_OFF_NB);
    float* decS = (float*)(smem + T_OFF_T);   // aliases tile buffers (post-MMA)
    const uint32_t sb = smem_u32(smem);

    const int tid  = threadIdx.x;
    const int wid  = tid >> 5;
    const int lane = tid & 31;
    const int t    = blockIdx.y;
    const int b0   = blockIdx.x * MB;
    const size_t wbase = (size_t)t * 256 * HID;

    if (tid < 256)
        sNB[tid] = (tid < INTERNAL) ? nodeb[t * INTERNAL + tid] : 0.f;

    const int wb  = wid >> 2;      // 0..3: 16-batch tile
    const int wn  = wid & 3;       // 0..3: 64-node tile
    const int grp = lane >> 2;
    const int kp  = lane & 3;

    const int lrow = lane & 15;
    const int lcol = (lane >> 4) * 4;
    const uint32_t aOff = (uint32_t)(((wb * 16 + lrow) * KSTR + lcol) * 4);
    uint32_t bOff[4];
#pragma unroll
    for (int pi = 0; pi < 4; pi++)
        bOff[pi] = (uint32_t)(((wn * 64 + pi * 16 + lrow) * KSTR + lcol) * 4);

    auto issue = [&](int c, int buf) {
        uint32_t base = sb + T_OFF_T + buf * T_BUF;
        if (tid < 256) {               // feats fp16: 64 x 4 = 256 slots
            int b = tid >> 2, q = tid & 3;
            size_t go = (size_t)(b0 + b) * HID + c * 32 + q * 8;
            uint32_t so = (uint32_t)((b * KSTR + q * 4) * 4);
            cp16(base + so, g_fH + go);
        }
#pragma unroll
        for (int rep = 0; rep < 2; rep++) {   // nodeW fp16: 256 x 4 = 1024 slots
            int i = tid + rep * 512;
            int n = i >> 2, q = i & 3;
            size_t go = wbase + (size_t)n * HID + c * 32 + q * 8;
            uint32_t so = (uint32_t)((n * KSTR + q * 4) * 4);
            cp16(base + T_FSZ + so, g_nwH + go);
        }
    };

    float acc[8][4];
#pragma unroll
    for (int ni = 0; ni < 8; ni++)
#pragma unroll
        for (int r = 0; r < 4; r++) acc[ni][r] = 0.f;

    issue(0, 0);
    cp_commit();

#pragma unroll
    for (int c = 0; c < T_NC; c++) {
        cp_wait0();
        __syncthreads();
        if (c + 1 < T_NC) { issue(c + 1, (c + 1) & 1); cp_commit(); }

        uint32_t fhB = sb + T_OFF_T + (c & 1) * T_BUF;
        uint32_t whB = fhB + T_FSZ;

#pragma unroll
        for (int s = 0; s < 2; s++) {
            uint32_t sB = s * 32;
            uint32_t ah0, ah1, ah2, ah3;
            ldsm4(ah0, ah1, ah2, ah3, fhB + aOff + sB);
#pragma unroll
            for (int pi = 0; pi < 4; pi++) {
                uint32_t h0, h1, h2, h3;
                ldsm4(h0, h1, h2, h3, whB + bOff[pi] + sB);
                mma16816h(acc[2 * pi],     ah0, ah1, ah2, ah3, h0, h2);
                mma16816h(acc[2 * pi + 1], ah0, ah1, ah2, ah3, h1, h3);
            }
        }
    }

    // dec tile aliases the MMA buffers: all compute must be done first
    __syncthreads();

    // ---- epilogue: + bias, sigmoid -> dec tile ----
#pragma unroll
    for (int ni = 0; ni < 8; ni++) {
        int nbase = wn * 64 + ni * 8 + kp * 2;
        int bb    = wb * 16 + grp;
#pragma unroll
        for (int r = 0; r < 4; r++) {
            int node = nbase + (r & 1);
            int b    = bb + (r >> 1) * 8;
            decS[node * DSTR + b] = sigmoidf_(acc[ni][r] + sNB[node]);
        }
    }
    __syncthreads();

    // ---- tree path products: 32 col-pairs x 16 groups, float2 ----
    {
        const int colp = (tid & 31) * 2;       // 0,2,..,62
        const int q    = tid >> 5;             // 0..15
        float* outCol = outAll + (size_t)t * TOTAL * BATCH + (b0 + colp);
        const float* decCol = decS + colp;

        if (q < 8) {
            // subtree rooted at level-3 node 7+q: 63 nodes
            const int rN = 7 + q;
            float2 v = make_float2(1.f, 1.f);
            int x = rN;
            while (x) {
                int p = (x - 1) >> 1;
                float2 d = *(const float2*)&decCol[p * DSTR];
                if (x == 2 * p + 1) { v.x *= d.x;        v.y *= d.y; }
                else                { v.x *= 1.f - d.x;  v.y *= 1.f - d.y; }
                x = p;
            }
            emit2<3>(outCol, decCol, rN, v);
        } else {
            // top 7 nodes (levels 0..2): group q-8 handles node q-8
            const int n = q - 8;
            if (n < 7) {
                float2 v = make_float2(1.f, 1.f);
                int x = n;
                while (x) {
                    int p = (x - 1) >> 1;
                    float2 d = *(const float2*)&decCol[p * DSTR];
                    if (x == 2 * p + 1) { v.x *= d.x;        v.y *= d.y; }
                    else                { v.x *= 1.f - d.x;  v.y *= 1.f - d.y; }
                    x = p;
                }
                stcs2(&outCol[(size_t)n * BATCH], v);
            }
        }
    }
}

// ---------------------------------------------------------------------------
extern "C" void kernel_launch(void* const* d_in, const int* in_sizes, int n_in,
                              void* d_out, int out_size) {
    const float* X     = (const float*)d_in[0];
    const float* W1    = (const float*)d_in[1];
    const float* b1    = (const float*)d_in[2];
    const float* W2    = (const float*)d_in[3];
    const float* b2    = (const float*)d_in[4];
    const float* nodeW = (const float*)d_in[5];
    const float* nodeb = (const float*)d_in[6];

    float* pred   = (float*)d_out;                               // [8192, 10]
    float* outAll = (float*)d_out + (size_t)BATCH * CLASS_NUM;   // [16, 511, 8192]

    cudaFuncSetAttribute(tree_mma_kernel, cudaFuncAttributeMaxDynamicSharedMemorySize,
                         TREE_SMEM);
    cudaFuncSetAttribute(gemm1_mma_kernel, cudaFuncAttributeMaxDynamicSharedMemorySize,
                         G_SMEM);

    conv_X_kernel<<<(BATCH * 200 + 255) / 256, 256>>>(X);
    conv_W1_kernel<<<HID, 256>>>(W1);
    conv_nodeW_kernel<<<TREES * 256 * HID / 256, 256>>>(nodeW);
    gemm1_mma_kernel<<<BATCH / G_MB, 512, G_SMEM>>>(b1);
    tree_mma_kernel<<<dim3(BATCH / MB, TREES), 512, TREE_SMEM>>>(nodeb, outAll);
    pred_kernel<<<BATCH / 32, 256>>>(W2, b2, pred);
}